// round 1
// baseline (speedup 1.0000x reference)
#include <cuda_runtime.h>
#include <cuda_bf16.h>
#include <math.h>

// ---------------------------------------------------------------------------
// VectorQuantizerEMA: N=32768 vectors, D=256, K=8192 codes
// Outputs concatenated in d_out (float32):
//   [0)            out (quant_st, NCHW)   32*256*32*32 = 8388608
//   [8388608)      loss                   1
//   [8388609)      perplexity             1
//   [8388610)      new_cluster_size       8192
//   [8396802)      new_embed              256*8192 = 2097152
//   [10493954)     new_ema_embed          2097152
// total = 12591106
// ---------------------------------------------------------------------------

#define NB      32
#define DD      256
#define HW      1024
#define NN      32768      // NB*HW
#define KK      8192

#define OUT_OFF      0
#define LOSS_OFF     8388608
#define PERP_OFF     8388609
#define NCS_OFF      8388610
#define NEWEMB_OFF   8396802
#define NEWEMA_OFF   10493954

// ---- scratch (device globals; no allocation allowed) ----
__device__ float g_X[NN * DD];        // 32 MB: inputs transposed to [N, D]
__device__ float g_enorm[KK];
__device__ int   g_idx[NN];
__device__ float g_counts[KK];
__device__ float g_invsm[KK];
__device__ float g_scal[4];           // [0] = loss accumulator

// ---------------------------------------------------------------------------
// K0: NCHW -> [N, D] transpose
// ---------------------------------------------------------------------------
__global__ void transpose_kernel(const float* __restrict__ in) {
    __shared__ float tile[32][33];
    int b  = blockIdx.z;
    int d0 = blockIdx.y * 32;
    int h0 = blockIdx.x * 32;
    int tx = threadIdx.x, ty = threadIdx.y;   // 32 x 8
    const float* src = in + (size_t)b * DD * HW;
#pragma unroll
    for (int i = 0; i < 32; i += 8)
        tile[ty + i][tx] = src[(d0 + ty + i) * HW + h0 + tx];
    __syncthreads();
#pragma unroll
    for (int i = 0; i < 32; i += 8)
        g_X[(size_t)(b * HW + h0 + ty + i) * DD + d0 + tx] = tile[tx][ty + i];
}

// ---------------------------------------------------------------------------
// K1: ||e_k||^2
// ---------------------------------------------------------------------------
__global__ void enorm_kernel(const float* __restrict__ embed) {
    int k = blockIdx.x * 256 + threadIdx.x;
    float s = 0.f;
#pragma unroll 8
    for (int d = 0; d < DD; d++) {
        float v = embed[(size_t)d * KK + k];
        s = fmaf(v, v, s);
    }
    g_enorm[k] = s;
}

// ---------------------------------------------------------------------------
// K3: init new_ema_embed section = 0.99*ema_embed, zero counts + scalars
// ---------------------------------------------------------------------------
__global__ void init_kernel(const float* __restrict__ ema, float* __restrict__ out) {
    int i = blockIdx.x * 256 + threadIdx.x;   // 0 .. 2097151
    out[NEWEMA_OFF + i] = 0.99f * ema[i];
    if (i < KK)  g_counts[i] = 0.f;
    if (i < 4)   g_scal[i]   = 0.f;
}

// ---------------------------------------------------------------------------
// K2: argmin GEMM.  Block = 128 rows x (full K loop, 128-wide tiles).
// 256 threads, thread tile 8 rows x 8 cols, cols paired as fma.rn.f32x2.
// ---------------------------------------------------------------------------
#define TN 128
#define TK 128
#define DC 16

__global__ __launch_bounds__(256, 2) void argmin_kernel(const float* __restrict__ embed) {
    __shared__ float Xs[DC][TN];
    __shared__ float Es[DC][TK];
    __shared__ float Ens[TK];
    __shared__ float bvs[TN][17];
    __shared__ int   bis[TN][17];

    int t  = threadIdx.x;
    int n0 = blockIdx.x * TN;
    int ty = t >> 4, tx = t & 15;
    int row0 = ty * 8, col0 = tx * 8;

    float bestv[8];
    int   besti[8];
#pragma unroll
    for (int r = 0; r < 8; r++) { bestv[r] = 3.4e38f; besti[r] = 0; }

    int nl = t >> 1;               // 0..127 (row for X staging)
    int dh = (t & 1) * 8;          // 0 or 8

    for (int k0 = 0; k0 < KK; k0 += TK) {
        __syncthreads();           // protect Ens / smem from prior epilogue readers
        if (t < TK) Ens[t] = g_enorm[k0 + t];

        unsigned long long acc[8][4];
#pragma unroll
        for (int r = 0; r < 8; r++)
#pragma unroll
            for (int j = 0; j < 4; j++) acc[r][j] = 0ull;

        for (int d0 = 0; d0 < DD; d0 += DC) {
            __syncthreads();
            // stage X tile (transposed into [d][n])
            {
                const float* px = &g_X[(size_t)(n0 + nl) * DD + d0 + dh];
                float4 v0 = *(const float4*)(px);
                float4 v1 = *(const float4*)(px + 4);
                Xs[dh + 0][nl] = v0.x; Xs[dh + 1][nl] = v0.y;
                Xs[dh + 2][nl] = v0.z; Xs[dh + 3][nl] = v0.w;
                Xs[dh + 4][nl] = v1.x; Xs[dh + 5][nl] = v1.y;
                Xs[dh + 6][nl] = v1.z; Xs[dh + 7][nl] = v1.w;
            }
            // stage E tile [d][k] (already k-contiguous)
#pragma unroll
            for (int i = 0; i < 8; i++) {
                int ii = t + i * 256;
                int dc = ii >> 7, k = ii & 127;
                Es[dc][k] = embed[(size_t)(d0 + dc) * KK + k0 + k];
            }
            __syncthreads();
#pragma unroll
            for (int dc = 0; dc < DC; dc++) {
                unsigned long long a2[8];
#pragma unroll
                for (int r = 0; r < 8; r++) {
                    unsigned ai = __float_as_uint(Xs[dc][row0 + r]);
                    asm("mov.b64 %0, {%1, %1};" : "=l"(a2[r]) : "r"(ai));
                }
                unsigned long long b2[4];
#pragma unroll
                for (int j = 0; j < 4; j++)
                    b2[j] = *(const unsigned long long*)&Es[dc][col0 + 2 * j];
#pragma unroll
                for (int r = 0; r < 8; r++)
#pragma unroll
                    for (int j = 0; j < 4; j++)
                        asm("fma.rn.f32x2 %0, %1, %2, %0;"
                            : "+l"(acc[r][j]) : "l"(a2[r]), "l"(b2[j]));
            }
        }
        // epilogue: dist = ||e||^2 - 2 x.e ; running min (first-index tie-break)
#pragma unroll
        for (int r = 0; r < 8; r++) {
#pragma unroll
            for (int j = 0; j < 4; j++) {
                union { unsigned long long u; float2 f; } cv; cv.u = acc[r][j];
                int c = col0 + 2 * j;
                float dA = fmaf(-2.f, cv.f.x, Ens[c]);
                float dB = fmaf(-2.f, cv.f.y, Ens[c + 1]);
                if (dA < bestv[r]) { bestv[r] = dA; besti[r] = k0 + c; }
                if (dB < bestv[r]) { bestv[r] = dB; besti[r] = k0 + c + 1; }
            }
        }
    }

    __syncthreads();
#pragma unroll
    for (int r = 0; r < 8; r++) { bvs[row0 + r][tx] = bestv[r]; bis[row0 + r][tx] = besti[r]; }
    __syncthreads();
    if (t < TN) {
        float bv = bvs[t][0]; int bi = bis[t][0];
#pragma unroll
        for (int j = 1; j < 16; j++) {
            float v = bvs[t][j]; int i2 = bis[t][j];
            if (v < bv || (v == bv && i2 < bi)) { bv = v; bi = i2; }
        }
        g_idx[n0 + t] = bi;
    }
}

// ---------------------------------------------------------------------------
// K4: gather quantize -> out (NCHW), accumulate e_latent_loss
// grid 256: blockIdx = b*8 + dgroup ; each block: one b, 32 d's, all hw
// ---------------------------------------------------------------------------
__global__ void gather_kernel(const float* __restrict__ inputs,
                              const float* __restrict__ embed,
                              float* __restrict__ out) {
    __shared__ int sidx[HW];
    __shared__ float sred[8];
    int b  = blockIdx.x >> 3;
    int d0 = (blockIdx.x & 7) * 32;
    int t  = threadIdx.x;

    for (int i = t; i < HW; i += 256) sidx[i] = g_idx[b * HW + i];
    __syncthreads();

    float lsum = 0.f;
    for (int d = d0; d < d0 + 32; d++) {
        const float* erow = embed + (size_t)d * KK;
        const float* irow = inputs + (size_t)b * DD * HW + (size_t)d * HW;
        float* orow       = out + OUT_OFF + (size_t)b * DD * HW + (size_t)d * HW;
#pragma unroll
        for (int hw = t; hw < HW; hw += 256) {
            float q = erow[sidx[hw]];
            float x = irow[hw];
            orow[hw] = q;
            float df = q - x;
            lsum = fmaf(df, df, lsum);
        }
    }
#pragma unroll
    for (int o = 16; o; o >>= 1) lsum += __shfl_down_sync(0xffffffffu, lsum, o);
    if ((t & 31) == 0) sred[t >> 5] = lsum;
    __syncthreads();
    if (t == 0) {
        float s = 0.f;
#pragma unroll
        for (int i = 0; i < 8; i++) s += sred[i];
        atomicAdd(&g_scal[0], s);
    }
}

// ---------------------------------------------------------------------------
// K5: scatter dw into new_ema_embed section; counts histogram
// ---------------------------------------------------------------------------
__global__ void scatter_kernel(float* __restrict__ out) {
    int n = blockIdx.x;
    int d = threadIdx.x;
    int id = g_idx[n];
    float x = g_X[(size_t)n * DD + d];
    atomicAdd(&out[NEWEMA_OFF + (size_t)d * KK + id], 0.01f * x);
    if (d == 0) atomicAdd(&g_counts[id], 1.0f);
}

// ---------------------------------------------------------------------------
// K6: finalize scalars + new_cluster_size + 1/smoothed  (single block, 1024 thr)
// ---------------------------------------------------------------------------
__global__ void finalize_kernel(const float* __restrict__ cs, float* __restrict__ out) {
    __shared__ float sh[32];
    __shared__ float s_n;
    int t = threadIdx.x;
    float ncs_loc[8];
    float nsum = 0.f, psum = 0.f;
#pragma unroll
    for (int i = 0; i < 8; i++) {
        int k = t + i * 1024;
        float c = g_counts[k];
        float v = cs[k] * 0.99f + 0.01f * c;
        out[NCS_OFF + k] = v;
        ncs_loc[i] = v;
        nsum += v;
        float p = c * (1.0f / 32768.0f);
        psum += p * logf(p + 1e-10f);
    }
    // reduce nsum
#pragma unroll
    for (int o = 16; o; o >>= 1) nsum += __shfl_down_sync(0xffffffffu, nsum, o);
    if ((t & 31) == 0) sh[t >> 5] = nsum;
    __syncthreads();
    if (t < 32) {
        float v = sh[t];
#pragma unroll
        for (int o = 16; o; o >>= 1) v += __shfl_down_sync(0xffffffffu, v, o);
        if (t == 0) s_n = v;
    }
    __syncthreads();
    float n = s_n;
#pragma unroll
    for (int i = 0; i < 8; i++) {
        int k = t + i * 1024;
        float v = ncs_loc[i];
        g_invsm[k] = (n + v * 1e-5f) / (n * (v + 1e-5f));
    }
    __syncthreads();
#pragma unroll
    for (int o = 16; o; o >>= 1) psum += __shfl_down_sync(0xffffffffu, psum, o);
    if ((t & 31) == 0) sh[t >> 5] = psum;
    __syncthreads();
    if (t == 0) {
        float p = 0.f;
#pragma unroll
        for (int i = 0; i < 32; i++) p += sh[i];
        out[LOSS_OFF] = 0.25f * g_scal[0] * (1.0f / 8388608.0f);
        out[PERP_OFF] = expf(-p);
    }
}

// ---------------------------------------------------------------------------
// K7: new_embed = new_ema_embed * (1/smoothed)
// ---------------------------------------------------------------------------
__global__ void newembed_kernel(float* __restrict__ out) {
    int i = blockIdx.x * 256 + threadIdx.x;   // 0 .. 2097151
    int k = i & (KK - 1);
    out[NEWEMB_OFF + i] = out[NEWEMA_OFF + i] * g_invsm[k];
}

// ---------------------------------------------------------------------------
extern "C" void kernel_launch(void* const* d_in, const int* in_sizes, int n_in,
                              void* d_out, int out_size) {
    const float* inputs = (const float*)d_in[0];
    const float* embed  = (const float*)d_in[1];
    const float* cs     = (const float*)d_in[2];
    const float* ema    = (const float*)d_in[3];
    float* out = (float*)d_out;
    (void)in_sizes; (void)n_in; (void)out_size;

    transpose_kernel<<<dim3(32, 8, 32), dim3(32, 8)>>>(inputs);
    enorm_kernel<<<KK / 256, 256>>>(embed);
    init_kernel<<<(DD * KK) / 256, 256>>>(ema, out);
    argmin_kernel<<<NN / TN, 256>>>(embed);
    gather_kernel<<<256, 256>>>(inputs, embed, out);
    scatter_kernel<<<NN, DD>>>(out);
    finalize_kernel<<<1, 1024>>>(cs, out);
    newembed_kernel<<<(DD * KK) / 256, 256>>>(out);
}

// round 2
// speedup vs baseline: 1.0851x; 1.0851x over previous
#include <cuda_runtime.h>
#include <cuda_bf16.h>
#include <math.h>

// ---------------------------------------------------------------------------
// VectorQuantizerEMA: N=32768 vectors, D=256, K=8192 codes
// d_out layout (float32):
//   [0)            out (quant_st, NCHW)   8388608
//   [8388608)      loss                   1
//   [8388609)      perplexity             1
//   [8388610)      new_cluster_size       8192
//   [8396802)      new_embed              2097152
//   [10493954)     new_ema_embed          2097152
// ---------------------------------------------------------------------------

#define NB      32
#define DD      256
#define HW      1024
#define NN      32768
#define KK      8192

#define OUT_OFF      0
#define LOSS_OFF     8388608
#define PERP_OFF     8388609
#define NCS_OFF      8388610
#define NEWEMB_OFF   8396802
#define NEWEMA_OFF   10493954

#define TN 128
#define TK 128
#define DC 16
#define KSPLIT 8
#define KPJ (KK / KSPLIT)   // 1024

// ---- scratch (device globals; no allocation allowed) ----
__device__ float g_X[NN * DD];          // 32 MB transposed inputs [N, D]
__device__ float g_enorm[KK];
__device__ int   g_idx[NN];
__device__ float g_counts[KK];
__device__ float g_invsm[KK];
__device__ float g_scal[4];
__device__ float g_bv[NN * KSPLIT];     // per-slice best value
__device__ int   g_bi[NN * KSPLIT];     // per-slice best index

// ---------------------------------------------------------------------------
// K0: NCHW -> [N, D] transpose
// ---------------------------------------------------------------------------
__global__ void transpose_kernel(const float* __restrict__ in) {
    __shared__ float tile[32][33];
    int b  = blockIdx.z;
    int d0 = blockIdx.y * 32;
    int h0 = blockIdx.x * 32;
    int tx = threadIdx.x, ty = threadIdx.y;   // 32 x 8
    const float* src = in + (size_t)b * DD * HW;
#pragma unroll
    for (int i = 0; i < 32; i += 8)
        tile[ty + i][tx] = src[(d0 + ty + i) * HW + h0 + tx];
    __syncthreads();
#pragma unroll
    for (int i = 0; i < 32; i += 8)
        g_X[(size_t)(b * HW + h0 + ty + i) * DD + d0 + tx] = tile[tx][ty + i];
}

// ---------------------------------------------------------------------------
// K1: ||e_k||^2
// ---------------------------------------------------------------------------
__global__ void enorm_kernel(const float* __restrict__ embed) {
    int k = blockIdx.x * 256 + threadIdx.x;
    float s = 0.f;
#pragma unroll 8
    for (int d = 0; d < DD; d++) {
        float v = embed[(size_t)d * KK + k];
        s = fmaf(v, v, s);
    }
    g_enorm[k] = s;
}

// ---------------------------------------------------------------------------
// K3: init new_ema_embed = 0.99*ema_embed, zero counts + scalars
// ---------------------------------------------------------------------------
__global__ void init_kernel(const float* __restrict__ ema, float* __restrict__ out) {
    int i = blockIdx.x * 256 + threadIdx.x;
    out[NEWEMA_OFF + i] = 0.99f * ema[i];
    if (i < KK)  g_counts[i] = 0.f;
    if (i < 4)   g_scal[i]   = 0.f;
}

// ---------------------------------------------------------------------------
// K2: argmin GEMM, double-buffered, K-split into 8 slices per row-tile.
// Block = 128 rows x 1024 K-slice. 256 threads, thread tile 8x8 (f32x2).
// grid = 256 row-tiles * 8 slices = 2048 blocks.
// ---------------------------------------------------------------------------
__global__ __launch_bounds__(256, 2) void argmin_kernel(const float* __restrict__ embed) {
    __shared__ float Xs[2][DC][TN];
    __shared__ float Es[2][DC][TK];
    __shared__ float Ens[TK];

    int t   = threadIdx.x;
    int job = blockIdx.x;
    int n0  = (job >> 3) * TN;
    int ksl = job & 7;
    int kb  = ksl * KPJ;

    int ty = t >> 4, tx = t & 15;
    int row0 = ty * 8, col0 = tx * 8;

    // staging mappings (conflict-free)
    int xr  = t & 127;            // X row within tile
    int xd  = (t >> 7) * 8;       // X d-offset 0 or 8
    int edc = t >> 5;             // E d-row 0..7
    int ek  = (t & 31) * 4;       // E k-offset (float4)

    const float* Xrow = &g_X[(size_t)(n0 + xr) * DD + xd];

    float bestv[8];
    int   besti[8];
#pragma unroll
    for (int r = 0; r < 8; r++) { bestv[r] = 3.4e38f; besti[r] = 0; }

    for (int kc = 0; kc < KPJ; kc += TK) {
        int k0 = kb + kc;
        const float* ebase = embed + (size_t)edc * KK + k0 + ek;

        // ---- prologue: load tile 0 ----
        float4 xa = *(const float4*)(Xrow);
        float4 xb = *(const float4*)(Xrow + 4);
        float4 e0 = *(const float4*)(ebase);
        float4 e1 = *(const float4*)(ebase + (size_t)8 * KK);

        __syncthreads();                       // prior epilogue / last compute done
        if (t < TK) Ens[t] = g_enorm[k0 + t];

        Xs[0][xd + 0][xr] = xa.x; Xs[0][xd + 1][xr] = xa.y;
        Xs[0][xd + 2][xr] = xa.z; Xs[0][xd + 3][xr] = xa.w;
        Xs[0][xd + 4][xr] = xb.x; Xs[0][xd + 5][xr] = xb.y;
        Xs[0][xd + 6][xr] = xb.z; Xs[0][xd + 7][xr] = xb.w;
        *(float4*)&Es[0][edc][ek]     = e0;
        *(float4*)&Es[0][edc + 8][ek] = e1;

        // prefetch tile 1
        xa = *(const float4*)(Xrow + DC);
        xb = *(const float4*)(Xrow + DC + 4);
        e0 = *(const float4*)(ebase + (size_t)DC * KK);
        e1 = *(const float4*)(ebase + (size_t)(DC + 8) * KK);
        __syncthreads();

        unsigned long long acc[8][4];
#pragma unroll
        for (int r = 0; r < 8; r++)
#pragma unroll
            for (int j = 0; j < 4; j++) acc[r][j] = 0ull;

#pragma unroll 1
        for (int i = 0; i < DD / DC; i++) {
            int cur = i & 1;
            if (i < 15) {
                int nb = cur ^ 1;
                Xs[nb][xd + 0][xr] = xa.x; Xs[nb][xd + 1][xr] = xa.y;
                Xs[nb][xd + 2][xr] = xa.z; Xs[nb][xd + 3][xr] = xa.w;
                Xs[nb][xd + 4][xr] = xb.x; Xs[nb][xd + 5][xr] = xb.y;
                Xs[nb][xd + 6][xr] = xb.z; Xs[nb][xd + 7][xr] = xb.w;
                *(float4*)&Es[nb][edc][ek]     = e0;
                *(float4*)&Es[nb][edc + 8][ek] = e1;
            }
            if (i < 14) {
                int d0 = (i + 2) * DC;
                xa = *(const float4*)(Xrow + d0);
                xb = *(const float4*)(Xrow + d0 + 4);
                e0 = *(const float4*)(ebase + (size_t)d0 * KK);
                e1 = *(const float4*)(ebase + (size_t)(d0 + 8) * KK);
            }
            const float (*Xc)[TN] = Xs[cur];
            const float (*Ec)[TK] = Es[cur];
#pragma unroll 8
            for (int dc = 0; dc < DC; dc++) {
                float4 r03 = *(const float4*)&Xc[dc][row0];
                float4 r47 = *(const float4*)&Xc[dc][row0 + 4];
                unsigned long long a2[8];
                {
                    unsigned u;
                    u = __float_as_uint(r03.x); asm("mov.b64 %0, {%1, %1};" : "=l"(a2[0]) : "r"(u));
                    u = __float_as_uint(r03.y); asm("mov.b64 %0, {%1, %1};" : "=l"(a2[1]) : "r"(u));
                    u = __float_as_uint(r03.z); asm("mov.b64 %0, {%1, %1};" : "=l"(a2[2]) : "r"(u));
                    u = __float_as_uint(r03.w); asm("mov.b64 %0, {%1, %1};" : "=l"(a2[3]) : "r"(u));
                    u = __float_as_uint(r47.x); asm("mov.b64 %0, {%1, %1};" : "=l"(a2[4]) : "r"(u));
                    u = __float_as_uint(r47.y); asm("mov.b64 %0, {%1, %1};" : "=l"(a2[5]) : "r"(u));
                    u = __float_as_uint(r47.z); asm("mov.b64 %0, {%1, %1};" : "=l"(a2[6]) : "r"(u));
                    u = __float_as_uint(r47.w); asm("mov.b64 %0, {%1, %1};" : "=l"(a2[7]) : "r"(u));
                }
                float4 c03 = *(const float4*)&Ec[dc][col0];
                float4 c47 = *(const float4*)&Ec[dc][col0 + 4];
                unsigned long long b2[4];
                {
                    float2 p;
                    p.x = c03.x; p.y = c03.y; b2[0] = *(unsigned long long*)&p;
                    p.x = c03.z; p.y = c03.w; b2[1] = *(unsigned long long*)&p;
                    p.x = c47.x; p.y = c47.y; b2[2] = *(unsigned long long*)&p;
                    p.x = c47.z; p.y = c47.w; b2[3] = *(unsigned long long*)&p;
                }
#pragma unroll
                for (int r = 0; r < 8; r++)
#pragma unroll
                    for (int j = 0; j < 4; j++)
                        asm("fma.rn.f32x2 %0, %1, %2, %0;"
                            : "+l"(acc[r][j]) : "l"(a2[r]), "l"(b2[j]));
            }
            __syncthreads();
        }

        // epilogue: dist = ||e||^2 - 2 x.e ; running first-min
#pragma unroll
        for (int r = 0; r < 8; r++) {
#pragma unroll
            for (int j = 0; j < 4; j++) {
                union { unsigned long long u; float2 f; } cv; cv.u = acc[r][j];
                int c = col0 + 2 * j;
                float dA = fmaf(-2.f, cv.f.x, Ens[c]);
                float dB = fmaf(-2.f, cv.f.y, Ens[c + 1]);
                if (dA < bestv[r]) { bestv[r] = dA; besti[r] = k0 + c; }
                if (dB < bestv[r]) { bestv[r] = dB; besti[r] = k0 + c + 1; }
            }
        }
    }

    // reduce across the 16 col-threads (same ty) via shfl; tie-break smaller idx
#pragma unroll
    for (int r = 0; r < 8; r++) {
        float bv = bestv[r]; int bi = besti[r];
#pragma unroll
        for (int o = 8; o; o >>= 1) {
            float ov = __shfl_xor_sync(0xffffffffu, bv, o);
            int   oi = __shfl_xor_sync(0xffffffffu, bi, o);
            if (ov < bv || (ov == bv && oi < bi)) { bv = ov; bi = oi; }
        }
        if (tx == 0) {
            int row = n0 + row0 + r;
            g_bv[row * KSPLIT + ksl] = bv;
            g_bi[row * KSPLIT + ksl] = bi;
        }
    }
}

// ---------------------------------------------------------------------------
// K2b: merge K-slices (lexicographic (value, index) min = global first-min)
// ---------------------------------------------------------------------------
__global__ void merge_kernel() {
    int n = blockIdx.x * 256 + threadIdx.x;
    float bv = g_bv[n * KSPLIT];
    int   bi = g_bi[n * KSPLIT];
#pragma unroll
    for (int s = 1; s < KSPLIT; s++) {
        float v = g_bv[n * KSPLIT + s];
        int   i = g_bi[n * KSPLIT + s];
        if (v < bv || (v == bv && i < bi)) { bv = v; bi = i; }
    }
    g_idx[n] = bi;
}

// ---------------------------------------------------------------------------
// K4: gather quantize -> out (NCHW), accumulate e_latent_loss
// ---------------------------------------------------------------------------
__global__ void gather_kernel(const float* __restrict__ inputs,
                              const float* __restrict__ embed,
                              float* __restrict__ out) {
    __shared__ int sidx[HW];
    __shared__ float sred[8];
    int b  = blockIdx.x >> 3;
    int d0 = (blockIdx.x & 7) * 32;
    int t  = threadIdx.x;

    for (int i = t; i < HW; i += 256) sidx[i] = g_idx[b * HW + i];
    __syncthreads();

    float lsum = 0.f;
    for (int d = d0; d < d0 + 32; d++) {
        const float* erow = embed + (size_t)d * KK;
        const float* irow = inputs + (size_t)b * DD * HW + (size_t)d * HW;
        float* orow       = out + OUT_OFF + (size_t)b * DD * HW + (size_t)d * HW;
#pragma unroll
        for (int hw = t; hw < HW; hw += 256) {
            float q = erow[sidx[hw]];
            float x = irow[hw];
            orow[hw] = q;
            float df = q - x;
            lsum = fmaf(df, df, lsum);
        }
    }
#pragma unroll
    for (int o = 16; o; o >>= 1) lsum += __shfl_down_sync(0xffffffffu, lsum, o);
    if ((t & 31) == 0) sred[t >> 5] = lsum;
    __syncthreads();
    if (t == 0) {
        float s = 0.f;
#pragma unroll
        for (int i = 0; i < 8; i++) s += sred[i];
        atomicAdd(&g_scal[0], s);
    }
}

// ---------------------------------------------------------------------------
// K5: scatter dw into new_ema_embed; counts histogram
// ---------------------------------------------------------------------------
__global__ void scatter_kernel(float* __restrict__ out) {
    int n = blockIdx.x;
    int d = threadIdx.x;
    int id = g_idx[n];
    float x = g_X[(size_t)n * DD + d];
    atomicAdd(&out[NEWEMA_OFF + (size_t)d * KK + id], 0.01f * x);
    if (d == 0) atomicAdd(&g_counts[id], 1.0f);
}

// ---------------------------------------------------------------------------
// K6: finalize scalars + new_cluster_size + 1/smoothed
// ---------------------------------------------------------------------------
__global__ void finalize_kernel(const float* __restrict__ cs, float* __restrict__ out) {
    __shared__ float sh[32];
    __shared__ float s_n;
    int t = threadIdx.x;
    float ncs_loc[8];
    float nsum = 0.f, psum = 0.f;
#pragma unroll
    for (int i = 0; i < 8; i++) {
        int k = t + i * 1024;
        float c = g_counts[k];
        float v = cs[k] * 0.99f + 0.01f * c;
        out[NCS_OFF + k] = v;
        ncs_loc[i] = v;
        nsum += v;
        float p = c * (1.0f / 32768.0f);
        psum += p * logf(p + 1e-10f);
    }
#pragma unroll
    for (int o = 16; o; o >>= 1) nsum += __shfl_down_sync(0xffffffffu, nsum, o);
    if ((t & 31) == 0) sh[t >> 5] = nsum;
    __syncthreads();
    if (t < 32) {
        float v = sh[t];
#pragma unroll
        for (int o = 16; o; o >>= 1) v += __shfl_down_sync(0xffffffffu, v, o);
        if (t == 0) s_n = v;
    }
    __syncthreads();
    float n = s_n;
#pragma unroll
    for (int i = 0; i < 8; i++) {
        int k = t + i * 1024;
        float v = ncs_loc[i];
        g_invsm[k] = (n + v * 1e-5f) / (n * (v + 1e-5f));
    }
    __syncthreads();
#pragma unroll
    for (int o = 16; o; o >>= 1) psum += __shfl_down_sync(0xffffffffu, psum, o);
    if ((t & 31) == 0) sh[t >> 5] = psum;
    __syncthreads();
    if (t == 0) {
        float p = 0.f;
#pragma unroll
        for (int i = 0; i < 32; i++) p += sh[i];
        out[LOSS_OFF] = 0.25f * g_scal[0] * (1.0f / 8388608.0f);
        out[PERP_OFF] = expf(-p);
    }
}

// ---------------------------------------------------------------------------
// K7: new_embed = new_ema_embed * (1/smoothed)
// ---------------------------------------------------------------------------
__global__ void newembed_kernel(float* __restrict__ out) {
    int i = blockIdx.x * 256 + threadIdx.x;
    int k = i & (KK - 1);
    out[NEWEMB_OFF + i] = out[NEWEMA_OFF + i] * g_invsm[k];
}

// ---------------------------------------------------------------------------
extern "C" void kernel_launch(void* const* d_in, const int* in_sizes, int n_in,
                              void* d_out, int out_size) {
    const float* inputs = (const float*)d_in[0];
    const float* embed  = (const float*)d_in[1];
    const float* cs     = (const float*)d_in[2];
    const float* ema    = (const float*)d_in[3];
    float* out = (float*)d_out;
    (void)in_sizes; (void)n_in; (void)out_size;

    transpose_kernel<<<dim3(32, 8, 32), dim3(32, 8)>>>(inputs);
    enorm_kernel<<<KK / 256, 256>>>(embed);
    init_kernel<<<(DD * KK) / 256, 256>>>(ema, out);
    argmin_kernel<<<(NN / TN) * KSPLIT, 256>>>(embed);
    merge_kernel<<<NN / 256, 256>>>();
    gather_kernel<<<256, 256>>>(inputs, embed, out);
    scatter_kernel<<<NN, DD>>>(out);
    finalize_kernel<<<1, 1024>>>(cs, out);
    newembed_kernel<<<(DD * KK) / 256, 256>>>(out);
}

// round 5
// speedup vs baseline: 2.2513x; 2.0747x over previous
#include <cuda_runtime.h>
#include <cuda_bf16.h>
#include <math.h>
#include <cstdint>

// ---------------------------------------------------------------------------
// VectorQuantizerEMA: N=32768 vectors, D=256, K=8192 codes — mma.sync argmin
// d_out layout (float32):
//   [0)          out (quant_st NCHW) 8388608
//   [8388608)    loss 1
//   [8388609)    perplexity 1
//   [8388610)    new_cluster_size 8192
//   [8396802)    new_embed 2097152
//   [10493954)   new_ema_embed 2097152
// ---------------------------------------------------------------------------

#define NB      32
#define DD      256
#define HW      1024
#define NN      32768
#define KK      8192

#define OUT_OFF      0
#define LOSS_OFF     8388608
#define PERP_OFF     8388609
#define NCS_OFF      8388610
#define NEWEMB_OFF   8396802
#define NEWEMA_OFF   10493954

#define KSPLIT  4
#define KPS     (KK / KSPLIT)     // 2048 codes per slice
#define KSLOT   (KSPLIT * 4)      // 16 disjoint candidate slots per row

// ---- scratch (device globals; no allocation allowed) ----
__device__ float          g_X[NN * DD];      // fp32 transposed inputs [N,D]
__device__ __nv_bfloat16  g_Xh[NN * DD];
__device__ __nv_bfloat16  g_Xl[NN * DD];
__device__ float          g_EtF[KK * DD];    // fp32 E^T [K,D]
__device__ __nv_bfloat16  g_Eth[KK * DD];
__device__ __nv_bfloat16  g_Etl[KK * DD];
__device__ float g_enorm[KK];
__device__ int   g_idx[NN];
__device__ int   g_c1[NN];
__device__ int   g_c2[NN];
__device__ float g_sv1[NN * KSLOT];
__device__ float g_sv2[NN * KSLOT];
__device__ int   g_si1[NN * KSLOT];
__device__ int   g_si2[NN * KSLOT];
__device__ float g_counts[KK];
__device__ float g_invsm[KK];
__device__ float g_scal[4];

// ===========================================================================
// helpers
// ===========================================================================
__device__ __forceinline__ uint32_t smem_to_u32(const void* p) {
    uint32_t a;
    asm("{ .reg .u64 t; cvta.to.shared.u64 t, %1; cvt.u32.u64 %0, t; }"
        : "=r"(a) : "l"(p));
    return a;
}
__device__ __forceinline__ void ldsm4(uint32_t* r, uint32_t addr) {
    asm volatile("ldmatrix.sync.aligned.m8n8.x4.shared.b16 {%0,%1,%2,%3}, [%4];"
                 : "=r"(r[0]), "=r"(r[1]), "=r"(r[2]), "=r"(r[3]) : "r"(addr));
}
__device__ __forceinline__ void mma16816(float* c, const uint32_t* a, const uint32_t* b) {
    asm volatile(
        "mma.sync.aligned.m16n8k16.row.col.f32.bf16.bf16.f32 "
        "{%0,%1,%2,%3}, {%4,%5,%6,%7}, {%8,%9}, {%0,%1,%2,%3};"
        : "+f"(c[0]), "+f"(c[1]), "+f"(c[2]), "+f"(c[3])
        : "r"(a[0]), "r"(a[1]), "r"(a[2]), "r"(a[3]), "r"(b[0]), "r"(b[1]));
}
__device__ __forceinline__ void cp16(uint32_t dst, const void* src) {
    asm volatile("cp.async.cg.shared.global [%0], [%1], 16;"
                 :: "r"(dst), "l"(src) : "memory");
}
#define CP_COMMIT() asm volatile("cp.async.commit_group;" ::: "memory")

// smem: A [hl][kc][128 rows][128B swizzled] = 128KB ; B [buf][hl][128 codes][128B] = 64KB
#define SMEM_A   0
#define SMEM_B   131072
#define SMEM_TOT 196608

// ---------------------------------------------------------------------------
// K0: NCHW -> [N,D]; fp32 + bf16 hi/lo split
// ---------------------------------------------------------------------------
__global__ void transpose_kernel(const float* __restrict__ in) {
    __shared__ float tile[32][33];
    int b  = blockIdx.z;
    int d0 = blockIdx.y * 32;
    int h0 = blockIdx.x * 32;
    int tx = threadIdx.x, ty = threadIdx.y;   // 32 x 8
    const float* src = in + (size_t)b * DD * HW;
#pragma unroll
    for (int i = 0; i < 32; i += 8)
        tile[ty + i][tx] = src[(d0 + ty + i) * HW + h0 + tx];
    __syncthreads();
#pragma unroll
    for (int i = 0; i < 32; i += 8) {
        float v = tile[tx][ty + i];
        size_t o = (size_t)(b * HW + h0 + ty + i) * DD + d0 + tx;
        g_X[o] = v;
        __nv_bfloat16 hi = __float2bfloat16_rn(v);
        g_Xh[o] = hi;
        g_Xl[o] = __float2bfloat16_rn(v - __bfloat162float(hi));
    }
}

// ---------------------------------------------------------------------------
// K0b: embed [D,K] -> E^T [K,D] fp32 + bf16 hi/lo
// ---------------------------------------------------------------------------
__global__ void etrans_kernel(const float* __restrict__ embed) {
    __shared__ float tile[32][33];
    int k0 = blockIdx.x * 32;
    int d0 = blockIdx.y * 32;
    int tx = threadIdx.x, ty = threadIdx.y;   // 32 x 8
#pragma unroll
    for (int i = 0; i < 32; i += 8)
        tile[ty + i][tx] = embed[(size_t)(d0 + ty + i) * KK + k0 + tx];
    __syncthreads();
#pragma unroll
    for (int i = 0; i < 32; i += 8) {
        float v = tile[tx][ty + i];
        size_t o = (size_t)(k0 + ty + i) * DD + d0 + tx;
        g_EtF[o] = v;
        __nv_bfloat16 hi = __float2bfloat16_rn(v);
        g_Eth[o] = hi;
        g_Etl[o] = __float2bfloat16_rn(v - __bfloat162float(hi));
    }
}

// ---------------------------------------------------------------------------
// K1: ||e_k||^2 (fp32 exact)
// ---------------------------------------------------------------------------
__global__ void enorm_kernel(const float* __restrict__ embed) {
    int k = blockIdx.x * 256 + threadIdx.x;
    float s = 0.f;
#pragma unroll 8
    for (int d = 0; d < DD; d++) {
        float v = embed[(size_t)d * KK + k];
        s = fmaf(v, v, s);
    }
    g_enorm[k] = s;
}

// ---------------------------------------------------------------------------
// K3: init new_ema_embed = 0.99*ema, zero counts/scalars
// ---------------------------------------------------------------------------
__global__ void init_kernel(const float* __restrict__ ema, float* __restrict__ out) {
    int i = blockIdx.x * 256 + threadIdx.x;
    out[NEWEMA_OFF + i] = 0.99f * ema[i];
    if (i < KK)  g_counts[i] = 0.f;
    if (i < 4)   g_scal[i]   = 0.f;
}

// ---------------------------------------------------------------------------
// B-chunk producer: 128 codes x 64 d (hi+lo) via cp.async into buffer `buf`
// ---------------------------------------------------------------------------
__device__ __forceinline__ void issueB(uint32_t sb, int buf, int c0, int kc, int tid) {
#pragma unroll
    for (int i = 0; i < 8; ++i) {
        int v = tid + i * 256;            // 0..2047
        int hl = v >> 10;
        int u = v & 1023;
        int code = u >> 3, g = u & 7;
        const __nv_bfloat16* src = hl ? g_Etl : g_Eth;
        const void* s = &src[(size_t)(c0 + code) * DD + kc * 64 + g * 8];
        uint32_t d = sb + SMEM_B + buf * 32768 + hl * 16384 + code * 128
                   + (uint32_t)((g ^ (code & 7)) << 4);
        cp16(d, s);
    }
    CP_COMMIT();
}

// ---------------------------------------------------------------------------
// K2: mma.sync argmin. CTA = 128 rows x 2048-code slice. 8 warps (2x4).
// 3-pass split bf16: S = Xh*Eh + Xh*El + Xl*Eh. Top-2 per row per slot.
// Each (slice, wn) pair is a DISJOINT code subset -> its own candidate slot.
// ---------------------------------------------------------------------------
__global__ __launch_bounds__(256, 1) void argmin_mma_kernel() {
    extern __shared__ char smem[];
    uint32_t sb = smem_to_u32(smem);
    int tid  = threadIdx.x;
    int lane = tid & 31, wid = tid >> 5;
    int wm = wid >> 2, wn = wid & 3;
    int mt = blockIdx.x >> 2, slice = blockIdx.x & 3;
    int n0 = mt * 128;
    int cs0 = slice * KPS;

    // ---- stage A (resident): 128 rows x 256 d, hi+lo, swizzled ----
#pragma unroll
    for (int hl = 0; hl < 2; ++hl) {
        const __nv_bfloat16* src = hl ? g_Xl : g_Xh;
#pragma unroll
        for (int i = 0; i < 16; ++i) {
            int v = tid + i * 256;        // 0..4095
            int row = v >> 5, gg = v & 31;
            int kc = gg >> 3, g = gg & 7;
            uint32_t off = SMEM_A + hl * 65536 + kc * 16384 + row * 128
                         + (uint32_t)((g ^ (row & 7)) << 4);
            *(uint4*)(smem + off) =
                *(const uint4*)&src[(size_t)(n0 + row) * DD + kc * 64 + g * 8];
        }
    }

    // ---- prologue: prefetch B chunks 0,1 ----
    issueB(sb, 0, cs0 + 0 * 128, 0, tid);
    issueB(sb, 1, cs0 + 0 * 128, 1, tid);

    float acc[4][4][4];
#pragma unroll
    for (int m = 0; m < 4; ++m)
#pragma unroll
        for (int n = 0; n < 4; ++n)
#pragma unroll
            for (int q = 0; q < 4; ++q) acc[m][n][q] = 0.f;

    float t1v[8], t2v[8];
    int   t1i[8], t2i[8];
#pragma unroll
    for (int s = 0; s < 8; ++s) { t1v[s] = 3.4e38f; t2v[s] = 3.4e38f; t1i[s] = 0; t2i[s] = 0; }

    // per-lane ldmatrix address components
    int j   = lane >> 3, rwi = lane & 7;
    int arow = wm * 64 + rwi + ((j & 1) << 3);
    int agsel = j >> 1;
    int arx  = arow & 7;
    uint32_t aBase = sb + SMEM_A + (uint32_t)arow * 128;
    int crow = wn * 32 + ((j >> 1) << 3) + rwi;
    int bgsel = j & 1;
    int crx  = crow & 7;
    uint32_t bBase = sb + SMEM_B + (uint32_t)crow * 128;

    int tid4 = lane & 3;

#pragma unroll 1
    for (int it = 0; it < 64; ++it) {
        int kc = it & 3, buf = it & 1;
        if (it < 63) asm volatile("cp.async.wait_group 1;" ::: "memory");
        else         asm volatile("cp.async.wait_group 0;" ::: "memory");
        __syncthreads();

#pragma unroll
        for (int kk = 0; kk < 4; ++kk) {
            uint32_t ah[4][4], al[4][4], bh[2][4], bl[2][4];
            uint32_t ga = (uint32_t)(((2 * kk + agsel) ^ arx) << 4);
            uint32_t gb = (uint32_t)(((2 * kk + bgsel) ^ crx) << 4);
#pragma unroll
            for (int m = 0; m < 4; ++m) {
                ldsm4(ah[m], aBase + kc * 16384 + m * 2048 + ga);
                ldsm4(al[m], aBase + 65536 + kc * 16384 + m * 2048 + ga);
            }
#pragma unroll
            for (int np = 0; np < 2; ++np) {
                ldsm4(bh[np], bBase + buf * 32768 + np * 2048 + gb);
                ldsm4(bl[np], bBase + buf * 32768 + 16384 + np * 2048 + gb);
            }
#pragma unroll
            for (int m = 0; m < 4; ++m)
#pragma unroll
                for (int n = 0; n < 4; ++n) {
                    const uint32_t* bhp = &bh[n >> 1][(n & 1) * 2];
                    const uint32_t* blp = &bl[n >> 1][(n & 1) * 2];
                    mma16816(acc[m][n], ah[m], bhp);
                    mma16816(acc[m][n], ah[m], blp);
                    mma16816(acc[m][n], al[m], bhp);
                }
        }
        __syncthreads();
        if (it + 2 < 64) {
            int it2 = it + 2;
            issueB(sb, it2 & 1, cs0 + (it2 >> 2) * 128, it2 & 3, tid);
        }

        if (kc == 3) {
            // epilogue for this 128-code tile
            int nt = it >> 2;
            int cb = cs0 + nt * 128 + wn * 32 + tid4 * 2;
#pragma unroll
            for (int m = 0; m < 4; ++m) {
#pragma unroll
                for (int n = 0; n < 4; ++n) {
                    int c = cb + n * 8;
                    float2 en = *(const float2*)&g_enorm[c];
                    float d0 = fmaf(-2.f, acc[m][n][0], en.x);
                    float d1 = fmaf(-2.f, acc[m][n][1], en.y);
                    float d2 = fmaf(-2.f, acc[m][n][2], en.x);
                    float d3 = fmaf(-2.f, acc[m][n][3], en.y);
                    int s0 = m * 2, s1 = m * 2 + 1;
                    if (d0 < t1v[s0]) { t2v[s0] = t1v[s0]; t2i[s0] = t1i[s0]; t1v[s0] = d0; t1i[s0] = c; }
                    else if (d0 < t2v[s0]) { t2v[s0] = d0; t2i[s0] = c; }
                    if (d1 < t1v[s0]) { t2v[s0] = t1v[s0]; t2i[s0] = t1i[s0]; t1v[s0] = d1; t1i[s0] = c + 1; }
                    else if (d1 < t2v[s0]) { t2v[s0] = d1; t2i[s0] = c + 1; }
                    if (d2 < t1v[s1]) { t2v[s1] = t1v[s1]; t2i[s1] = t1i[s1]; t1v[s1] = d2; t1i[s1] = c; }
                    else if (d2 < t2v[s1]) { t2v[s1] = d2; t2i[s1] = c; }
                    if (d3 < t1v[s1]) { t2v[s1] = t1v[s1]; t2i[s1] = t1i[s1]; t1v[s1] = d3; t1i[s1] = c + 1; }
                    else if (d3 < t2v[s1]) { t2v[s1] = d3; t2i[s1] = c + 1; }
#pragma unroll
                    for (int q = 0; q < 4; ++q) acc[m][n][q] = 0.f;
                }
            }
        }
    }

    // ---- merge top-2 across the 4 threads that share each row ----
#pragma unroll
    for (int s = 0; s < 8; ++s) {
        float v1 = t1v[s], v2 = t2v[s];
        int   i1 = t1i[s], i2 = t2i[s];
#pragma unroll
        for (int off = 1; off <= 2; off <<= 1) {
            float ov1 = __shfl_xor_sync(0xffffffffu, v1, off);
            int   oi1 = __shfl_xor_sync(0xffffffffu, i1, off);
            float ov2 = __shfl_xor_sync(0xffffffffu, v2, off);
            int   oi2 = __shfl_xor_sync(0xffffffffu, i2, off);
            if (ov1 < v1 || (ov1 == v1 && oi1 < i1)) {
                float nv2; int ni2;
                if (v1 < ov2 || (v1 == ov2 && i1 < oi2)) { nv2 = v1; ni2 = i1; }
                else { nv2 = ov2; ni2 = oi2; }
                v1 = ov1; i1 = oi1; v2 = nv2; i2 = ni2;
            } else {
                if (ov1 < v2 || (ov1 == v2 && oi1 < i2)) { v2 = ov1; i2 = oi1; }
            }
        }
        if (tid4 == 0) {
            int grp = lane >> 2;
            int row = n0 + wm * 64 + (s >> 1) * 16 + (s & 1) * 8 + grp;
            int slot = slice * 4 + wn;          // disjoint code subset per slot
            g_sv1[row * KSLOT + slot] = v1;
            g_si1[row * KSLOT + slot] = i1;
            g_sv2[row * KSLOT + slot] = v2;
            g_si2[row * KSLOT + slot] = i2;
        }
    }
}

// ---------------------------------------------------------------------------
// K2b: merge slots -> global top-2 candidates per row
// ---------------------------------------------------------------------------
__global__ void merge_kernel() {
    int row = blockIdx.x * 256 + threadIdx.x;
    float b1v = 3.4e38f, b2v = 3.4e38f;
    int   b1i = 0,       b2i = 0;
#pragma unroll
    for (int s = 0; s < KSLOT; ++s) {
        float v1 = g_sv1[row * KSLOT + s]; int i1 = g_si1[row * KSLOT + s];
        float v2 = g_sv2[row * KSLOT + s]; int i2 = g_si2[row * KSLOT + s];
        if (v1 < b1v || (v1 == b1v && i1 < b1i)) { b2v = b1v; b2i = b1i; b1v = v1; b1i = i1; }
        else if (v1 < b2v || (v1 == b2v && i1 < b2i)) { b2v = v1; b2i = i1; }
        if (v2 < b1v || (v2 == b1v && i2 < b1i)) { b2v = b1v; b2i = b1i; b1v = v2; b1i = i2; }
        else if (v2 < b2v || (v2 == b2v && i2 < b2i)) { b2v = v2; b2i = i2; }
    }
    g_c1[row] = b1i;
    g_c2[row] = b2i;
}

// ---------------------------------------------------------------------------
// K2c: exact fp64 rerank of the two candidates per row (1 warp per row)
// ---------------------------------------------------------------------------
__global__ void rerank_kernel() {
    int row = blockIdx.x * 8 + (threadIdx.x >> 5);
    int lane = threadIdx.x & 31;
    int c1 = g_c1[row], c2 = g_c2[row];
    const float4* xp = (const float4*)&g_X[(size_t)row * DD + lane * 8];
    float4 xa = xp[0], xb = xp[1];
    const float4* e1p = (const float4*)&g_EtF[(size_t)c1 * DD + lane * 8];
    const float4* e2p = (const float4*)&g_EtF[(size_t)c2 * DD + lane * 8];
    float4 ea = e1p[0], eb = e1p[1];
    float4 fa = e2p[0], fb = e2p[1];
    double s1 = 0.0, s2 = 0.0, d;
    d = (double)xa.x - ea.x; s1 += d * d;   d = (double)xa.x - fa.x; s2 += d * d;
    d = (double)xa.y - ea.y; s1 += d * d;   d = (double)xa.y - fa.y; s2 += d * d;
    d = (double)xa.z - ea.z; s1 += d * d;   d = (double)xa.z - fa.z; s2 += d * d;
    d = (double)xa.w - ea.w; s1 += d * d;   d = (double)xa.w - fa.w; s2 += d * d;
    d = (double)xb.x - eb.x; s1 += d * d;   d = (double)xb.x - fb.x; s2 += d * d;
    d = (double)xb.y - eb.y; s1 += d * d;   d = (double)xb.y - fb.y; s2 += d * d;
    d = (double)xb.z - eb.z; s1 += d * d;   d = (double)xb.z - fb.z; s2 += d * d;
    d = (double)xb.w - eb.w; s1 += d * d;   d = (double)xb.w - fb.w; s2 += d * d;
#pragma unroll
    for (int o = 16; o; o >>= 1) {
        s1 += __shfl_down_sync(0xffffffffu, s1, o);
        s2 += __shfl_down_sync(0xffffffffu, s2, o);
    }
    if (lane == 0) {
        int pick = (s2 < s1 || (s2 == s1 && c2 < c1)) ? c2 : c1;
        g_idx[row] = pick;
    }
}

// ---------------------------------------------------------------------------
// K4: gather quantize -> out (NCHW), accumulate e_latent_loss
// ---------------------------------------------------------------------------
__global__ void gather_kernel(const float* __restrict__ inputs,
                              const float* __restrict__ embed,
                              float* __restrict__ out) {
    __shared__ int sidx[HW];
    __shared__ float sred[8];
    int b  = blockIdx.x >> 3;
    int d0 = (blockIdx.x & 7) * 32;
    int t  = threadIdx.x;

    for (int i = t; i < HW; i += 256) sidx[i] = g_idx[b * HW + i];
    __syncthreads();

    float lsum = 0.f;
    for (int d = d0; d < d0 + 32; d++) {
        const float* erow = embed + (size_t)d * KK;
        const float* irow = inputs + (size_t)b * DD * HW + (size_t)d * HW;
        float* orow       = out + OUT_OFF + (size_t)b * DD * HW + (size_t)d * HW;
#pragma unroll
        for (int hw = t; hw < HW; hw += 256) {
            float q = erow[sidx[hw]];
            float x = irow[hw];
            orow[hw] = q;
            float df = q - x;
            lsum = fmaf(df, df, lsum);
        }
    }
#pragma unroll
    for (int o = 16; o; o >>= 1) lsum += __shfl_down_sync(0xffffffffu, lsum, o);
    if ((t & 31) == 0) sred[t >> 5] = lsum;
    __syncthreads();
    if (t == 0) {
        float s = 0.f;
#pragma unroll
        for (int i = 0; i < 8; i++) s += sred[i];
        atomicAdd(&g_scal[0], s);
    }
}

// ---------------------------------------------------------------------------
// K5: scatter dw into new_ema_embed; counts histogram
// ---------------------------------------------------------------------------
__global__ void scatter_kernel(float* __restrict__ out) {
    int n = blockIdx.x;
    int d = threadIdx.x;
    int id = g_idx[n];
    float x = g_X[(size_t)n * DD + d];
    atomicAdd(&out[NEWEMA_OFF + (size_t)d * KK + id], 0.01f * x);
    if (d == 0) atomicAdd(&g_counts[id], 1.0f);
}

// ---------------------------------------------------------------------------
// K6: finalize scalars + new_cluster_size + 1/smoothed
// ---------------------------------------------------------------------------
__global__ void finalize_kernel(const float* __restrict__ cs, float* __restrict__ out) {
    __shared__ float sh[32];
    __shared__ float s_n;
    int t = threadIdx.x;
    float ncs_loc[8];
    float nsum = 0.f, psum = 0.f;
#pragma unroll
    for (int i = 0; i < 8; i++) {
        int k = t + i * 1024;
        float c = g_counts[k];
        float v = cs[k] * 0.99f + 0.01f * c;
        out[NCS_OFF + k] = v;
        ncs_loc[i] = v;
        nsum += v;
        float p = c * (1.0f / 32768.0f);
        psum += p * logf(p + 1e-10f);
    }
#pragma unroll
    for (int o = 16; o; o >>= 1) nsum += __shfl_down_sync(0xffffffffu, nsum, o);
    if ((t & 31) == 0) sh[t >> 5] = nsum;
    __syncthreads();
    if (t < 32) {
        float v = sh[t];
#pragma unroll
        for (int o = 16; o; o >>= 1) v += __shfl_down_sync(0xffffffffu, v, o);
        if (t == 0) s_n = v;
    }
    __syncthreads();
    float n = s_n;
#pragma unroll
    for (int i = 0; i < 8; i++) {
        int k = t + i * 1024;
        float v = ncs_loc[i];
        g_invsm[k] = (n + v * 1e-5f) / (n * (v + 1e-5f));
    }
    __syncthreads();
#pragma unroll
    for (int o = 16; o; o >>= 1) psum += __shfl_down_sync(0xffffffffu, psum, o);
    if ((t & 31) == 0) sh[t >> 5] = psum;
    __syncthreads();
    if (t == 0) {
        float p = 0.f;
#pragma unroll
        for (int i = 0; i < 32; i++) p += sh[i];
        out[LOSS_OFF] = 0.25f * g_scal[0] * (1.0f / 8388608.0f);
        out[PERP_OFF] = expf(-p);
    }
}

// ---------------------------------------------------------------------------
// K7: new_embed = new_ema_embed * (1/smoothed)
// ---------------------------------------------------------------------------
__global__ void newembed_kernel(float* __restrict__ out) {
    int i = blockIdx.x * 256 + threadIdx.x;
    int k = i & (KK - 1);
    out[NEWEMB_OFF + i] = out[NEWEMA_OFF + i] * g_invsm[k];
}

// ---------------------------------------------------------------------------
extern "C" void kernel_launch(void* const* d_in, const int* in_sizes, int n_in,
                              void* d_out, int out_size) {
    const float* inputs = (const float*)d_in[0];
    const float* embed  = (const float*)d_in[1];
    const float* cs     = (const float*)d_in[2];
    const float* ema    = (const float*)d_in[3];
    float* out = (float*)d_out;
    (void)in_sizes; (void)n_in; (void)out_size;

    cudaFuncSetAttribute(argmin_mma_kernel,
                         cudaFuncAttributeMaxDynamicSharedMemorySize, SMEM_TOT);

    transpose_kernel<<<dim3(32, 8, 32), dim3(32, 8)>>>(inputs);
    etrans_kernel<<<dim3(KK / 32, DD / 32), dim3(32, 8)>>>(embed);
    enorm_kernel<<<KK / 256, 256>>>(embed);
    init_kernel<<<(DD * KK) / 256, 256>>>(ema, out);
    argmin_mma_kernel<<<(NN / 128) * KSPLIT, 256, SMEM_TOT>>>();
    merge_kernel<<<NN / 256, 256>>>();
    rerank_kernel<<<NN / 8, 256>>>();
    gather_kernel<<<256, 256>>>(inputs, embed, out);
    scatter_kernel<<<NN, DD>>>(out);
    finalize_kernel<<<1, 1024>>>(cs, out);
    newembed_kernel<<<(DD * KK) / 256, 256>>>(out);
}

// round 6
// speedup vs baseline: 3.6879x; 1.6381x over previous
#include <cuda_runtime.h>
#include <cuda_fp16.h>
#include <math.h>
#include <cstdint>

// ---------------------------------------------------------------------------
// VectorQuantizerEMA: N=32768 vectors, D=256, K=8192 codes
// Single-pass FP16 mma.sync argmin + exact fp64 top-4 rerank.
// d_out layout (float32):
//   [0)          out (quant_st NCHW) 8388608
//   [8388608)    loss 1
//   [8388609)    perplexity 1
//   [8388610)    new_cluster_size 8192
//   [8396802)    new_embed 2097152
//   [10493954)   new_ema_embed 2097152
// ---------------------------------------------------------------------------

#define NB      32
#define DD      256
#define HW      1024
#define NN      32768
#define KK      8192

#define OUT_OFF      0
#define LOSS_OFF     8388608
#define PERP_OFF     8388609
#define NCS_OFF      8388610
#define NEWEMB_OFF   8396802
#define NEWEMA_OFF   10493954

#define KSPLIT  4
#define KPS     (KK / KSPLIT)     // 2048 codes per slice
#define KSLOT   (KSPLIT * 4)      // 16 disjoint candidate slots per row

// ---- scratch (device globals; no allocation allowed) ----
__device__ float   g_X[NN * DD];      // fp32 transposed inputs [N,D]
__device__ __half  g_Xf[NN * DD];     // fp16 [N,D]
__device__ float   g_EtF[KK * DD];    // fp32 E^T [K,D]
__device__ __half  g_Ef[KK * DD];     // fp16 E^T [K,D]
__device__ float g_enorm[KK];
__device__ int   g_idx[NN];
__device__ int   g_cand[NN * 4];
__device__ float g_sv1[NN * KSLOT];
__device__ float g_sv2[NN * KSLOT];
__device__ int   g_si1[NN * KSLOT];
__device__ int   g_si2[NN * KSLOT];
__device__ float g_counts[KK];
__device__ float g_invsm[KK];
__device__ float g_scal[4];

// ===========================================================================
// helpers
// ===========================================================================
__device__ __forceinline__ uint32_t smem_to_u32(const void* p) {
    uint32_t a;
    asm("{ .reg .u64 t; cvta.to.shared.u64 t, %1; cvt.u32.u64 %0, t; }"
        : "=r"(a) : "l"(p));
    return a;
}
__device__ __forceinline__ void ldsm4(uint32_t* r, uint32_t addr) {
    asm volatile("ldmatrix.sync.aligned.m8n8.x4.shared.b16 {%0,%1,%2,%3}, [%4];"
                 : "=r"(r[0]), "=r"(r[1]), "=r"(r[2]), "=r"(r[3]) : "r"(addr));
}
__device__ __forceinline__ void mma16816(float* c, const uint32_t* a, const uint32_t* b) {
    asm volatile(
        "mma.sync.aligned.m16n8k16.row.col.f32.f16.f16.f32 "
        "{%0,%1,%2,%3}, {%4,%5,%6,%7}, {%8,%9}, {%0,%1,%2,%3};"
        : "+f"(c[0]), "+f"(c[1]), "+f"(c[2]), "+f"(c[3])
        : "r"(a[0]), "r"(a[1]), "r"(a[2]), "r"(a[3]), "r"(b[0]), "r"(b[1]));
}
__device__ __forceinline__ void cp16(uint32_t dst, const void* src) {
    asm volatile("cp.async.cg.shared.global [%0], [%1], 16;"
                 :: "r"(dst), "l"(src) : "memory");
}
#define CP_COMMIT() asm volatile("cp.async.commit_group;" ::: "memory")

// smem: A [kc(4)][128 rows][128B swizzled] = 64KB ; B [buf(2)][128 codes][128B] = 32KB
#define SMEM_A   0
#define SMEM_B   65536
#define SMEM_TOT 98304

// ---------------------------------------------------------------------------
// K0: NCHW -> [N,D]; fp32 + fp16
// ---------------------------------------------------------------------------
__global__ void transpose_kernel(const float* __restrict__ in) {
    __shared__ float tile[32][33];
    int b  = blockIdx.z;
    int d0 = blockIdx.y * 32;
    int h0 = blockIdx.x * 32;
    int tx = threadIdx.x, ty = threadIdx.y;   // 32 x 8
    const float* src = in + (size_t)b * DD * HW;
#pragma unroll
    for (int i = 0; i < 32; i += 8)
        tile[ty + i][tx] = src[(d0 + ty + i) * HW + h0 + tx];
    __syncthreads();
#pragma unroll
    for (int i = 0; i < 32; i += 8) {
        float v = tile[tx][ty + i];
        size_t o = (size_t)(b * HW + h0 + ty + i) * DD + d0 + tx;
        g_X[o]  = v;
        g_Xf[o] = __float2half_rn(v);
    }
}

// ---------------------------------------------------------------------------
// K0b: embed [D,K] -> E^T [K,D] fp32 + fp16
// ---------------------------------------------------------------------------
__global__ void etrans_kernel(const float* __restrict__ embed) {
    __shared__ float tile[32][33];
    int k0 = blockIdx.x * 32;
    int d0 = blockIdx.y * 32;
    int tx = threadIdx.x, ty = threadIdx.y;   // 32 x 8
#pragma unroll
    for (int i = 0; i < 32; i += 8)
        tile[ty + i][tx] = embed[(size_t)(d0 + ty + i) * KK + k0 + tx];
    __syncthreads();
#pragma unroll
    for (int i = 0; i < 32; i += 8) {
        float v = tile[tx][ty + i];
        size_t o = (size_t)(k0 + ty + i) * DD + d0 + tx;
        g_EtF[o] = v;
        g_Ef[o]  = __float2half_rn(v);
    }
}

// ---------------------------------------------------------------------------
// K1: ||e_k||^2 (fp32 exact)
// ---------------------------------------------------------------------------
__global__ void enorm_kernel(const float* __restrict__ embed) {
    int k = blockIdx.x * 256 + threadIdx.x;
    float s = 0.f;
#pragma unroll 8
    for (int d = 0; d < DD; d++) {
        float v = embed[(size_t)d * KK + k];
        s = fmaf(v, v, s);
    }
    g_enorm[k] = s;
}

// ---------------------------------------------------------------------------
// K3: init new_ema_embed = 0.99*ema, zero counts/scalars
// ---------------------------------------------------------------------------
__global__ void init_kernel(const float* __restrict__ ema, float* __restrict__ out) {
    int i = blockIdx.x * 256 + threadIdx.x;
    out[NEWEMA_OFF + i] = 0.99f * ema[i];
    if (i < KK)  g_counts[i] = 0.f;
    if (i < 4)   g_scal[i]   = 0.f;
}

// ---------------------------------------------------------------------------
// B-chunk producer: 128 codes x 64 d (fp16) via cp.async into buffer `buf`
// ---------------------------------------------------------------------------
__device__ __forceinline__ void issueB(uint32_t sb, int buf, int c0, int kc, int tid) {
#pragma unroll
    for (int i = 0; i < 4; ++i) {
        int v = tid + i * 256;            // 0..1023
        int code = v >> 3, g = v & 7;
        const void* s = &g_Ef[(size_t)(c0 + code) * DD + kc * 64 + g * 8];
        uint32_t d = sb + SMEM_B + buf * 16384 + code * 128
                   + (uint32_t)((g ^ (code & 7)) << 4);
        cp16(d, s);
    }
    CP_COMMIT();
}

// ---------------------------------------------------------------------------
// K2: fp16 mma.sync argmin. CTA = 128 rows x 2048-code slice. 8 warps (2x4).
// Single pass: S = Xf * Ef. Top-2 per row per (slice,wn) slot.
// ---------------------------------------------------------------------------
__global__ __launch_bounds__(256, 2) void argmin_mma_kernel() {
    extern __shared__ char smem[];
    uint32_t sb = smem_to_u32(smem);
    int tid  = threadIdx.x;
    int lane = tid & 31, wid = tid >> 5;
    int wm = wid >> 2, wn = wid & 3;
    int mt = blockIdx.x >> 2, slice = blockIdx.x & 3;
    int n0 = mt * 128;
    int cs0 = slice * KPS;

    // ---- stage A (resident): 128 rows x 256 d fp16, swizzled ----
#pragma unroll
    for (int i = 0; i < 16; ++i) {
        int v = tid + i * 256;            // 0..4095
        int kc = v >> 10;
        int u = v & 1023;
        int row = u >> 3, g = u & 7;
        uint32_t off = SMEM_A + kc * 16384 + row * 128
                     + (uint32_t)((g ^ (row & 7)) << 4);
        *(uint4*)(smem + off) =
            *(const uint4*)&g_Xf[(size_t)(n0 + row) * DD + kc * 64 + g * 8];
    }

    // ---- prologue: prefetch B chunks 0,1 ----
    issueB(sb, 0, cs0, 0, tid);
    issueB(sb, 1, cs0, 1, tid);

    float acc[4][4][4];
#pragma unroll
    for (int m = 0; m < 4; ++m)
#pragma unroll
        for (int n = 0; n < 4; ++n)
#pragma unroll
            for (int q = 0; q < 4; ++q) acc[m][n][q] = 0.f;

    float t1v[8], t2v[8];
    int   t1i[8], t2i[8];
#pragma unroll
    for (int s = 0; s < 8; ++s) { t1v[s] = 3.4e38f; t2v[s] = 3.4e38f; t1i[s] = 0; t2i[s] = 0; }

    // per-lane ldmatrix address components
    int j   = lane >> 3, rwi = lane & 7;
    int arow = wm * 64 + rwi + ((j & 1) << 3);
    int agsel = j >> 1;
    int arx  = arow & 7;
    uint32_t aBase = sb + SMEM_A + (uint32_t)arow * 128;
    int crow = wn * 32 + ((j >> 1) << 3) + rwi;
    int bgsel = j & 1;
    int crx  = crow & 7;
    uint32_t bBase = sb + SMEM_B + (uint32_t)crow * 128;

    int tid4 = lane & 3;

#pragma unroll 1
    for (int it = 0; it < 64; ++it) {
        int kc = it & 3, buf = it & 1;
        if (it < 63) asm volatile("cp.async.wait_group 1;" ::: "memory");
        else         asm volatile("cp.async.wait_group 0;" ::: "memory");
        __syncthreads();

#pragma unroll
        for (int kk = 0; kk < 4; ++kk) {
            uint32_t ah[4][4], bh[2][4];
            uint32_t ga = (uint32_t)(((2 * kk + agsel) ^ arx) << 4);
            uint32_t gb = (uint32_t)(((2 * kk + bgsel) ^ crx) << 4);
#pragma unroll
            for (int m = 0; m < 4; ++m)
                ldsm4(ah[m], aBase + kc * 16384 + m * 2048 + ga);
#pragma unroll
            for (int np = 0; np < 2; ++np)
                ldsm4(bh[np], bBase + buf * 16384 + np * 2048 + gb);
#pragma unroll
            for (int m = 0; m < 4; ++m)
#pragma unroll
                for (int n = 0; n < 4; ++n)
                    mma16816(acc[m][n], ah[m], &bh[n >> 1][(n & 1) * 2]);
        }
        __syncthreads();
        if (it + 2 < 64) {
            int it2 = it + 2;
            issueB(sb, it2 & 1, cs0 + (it2 >> 2) * 128, it2 & 3, tid);
        }

        if (kc == 3) {
            // epilogue for this 128-code tile
            int nt = it >> 2;
            int cb = cs0 + nt * 128 + wn * 32 + tid4 * 2;
#pragma unroll
            for (int m = 0; m < 4; ++m) {
#pragma unroll
                for (int n = 0; n < 4; ++n) {
                    int c = cb + n * 8;
                    float2 en = *(const float2*)&g_enorm[c];
                    float d0 = fmaf(-2.f, acc[m][n][0], en.x);
                    float d1 = fmaf(-2.f, acc[m][n][1], en.y);
                    float d2 = fmaf(-2.f, acc[m][n][2], en.x);
                    float d3 = fmaf(-2.f, acc[m][n][3], en.y);
                    int s0 = m * 2, s1 = m * 2 + 1;
                    if (d0 < t1v[s0]) { t2v[s0] = t1v[s0]; t2i[s0] = t1i[s0]; t1v[s0] = d0; t1i[s0] = c; }
                    else if (d0 < t2v[s0]) { t2v[s0] = d0; t2i[s0] = c; }
                    if (d1 < t1v[s0]) { t2v[s0] = t1v[s0]; t2i[s0] = t1i[s0]; t1v[s0] = d1; t1i[s0] = c + 1; }
                    else if (d1 < t2v[s0]) { t2v[s0] = d1; t2i[s0] = c + 1; }
                    if (d2 < t1v[s1]) { t2v[s1] = t1v[s1]; t2i[s1] = t1i[s1]; t1v[s1] = d2; t1i[s1] = c; }
                    else if (d2 < t2v[s1]) { t2v[s1] = d2; t2i[s1] = c; }
                    if (d3 < t1v[s1]) { t2v[s1] = t1v[s1]; t2i[s1] = t1i[s1]; t1v[s1] = d3; t1i[s1] = c + 1; }
                    else if (d3 < t2v[s1]) { t2v[s1] = d3; t2i[s1] = c + 1; }
#pragma unroll
                    for (int q = 0; q < 4; ++q) acc[m][n][q] = 0.f;
                }
            }
        }
    }

    // ---- merge top-2 across the 4 threads that share each row ----
#pragma unroll
    for (int s = 0; s < 8; ++s) {
        float v1 = t1v[s], v2 = t2v[s];
        int   i1 = t1i[s], i2 = t2i[s];
#pragma unroll
        for (int off = 1; off <= 2; off <<= 1) {
            float ov1 = __shfl_xor_sync(0xffffffffu, v1, off);
            int   oi1 = __shfl_xor_sync(0xffffffffu, i1, off);
            float ov2 = __shfl_xor_sync(0xffffffffu, v2, off);
            int   oi2 = __shfl_xor_sync(0xffffffffu, i2, off);
            if (ov1 < v1 || (ov1 == v1 && oi1 < i1)) {
                float nv2; int ni2;
                if (v1 < ov2 || (v1 == ov2 && i1 < oi2)) { nv2 = v1; ni2 = i1; }
                else { nv2 = ov2; ni2 = oi2; }
                v1 = ov1; i1 = oi1; v2 = nv2; i2 = ni2;
            } else {
                if (ov1 < v2 || (ov1 == v2 && oi1 < i2)) { v2 = ov1; i2 = oi1; }
            }
        }
        if (tid4 == 0) {
            int grp = lane >> 2;
            int row = n0 + wm * 64 + (s >> 1) * 16 + (s & 1) * 8 + grp;
            int slot = slice * 4 + wn;          // disjoint code subset per slot
            g_sv1[row * KSLOT + slot] = v1;
            g_si1[row * KSLOT + slot] = i1;
            g_sv2[row * KSLOT + slot] = v2;
            g_si2[row * KSLOT + slot] = i2;
        }
    }
}

// ---------------------------------------------------------------------------
// K2b: merge 16 slots (32 candidates) -> global top-4 per row
// ---------------------------------------------------------------------------
__device__ __forceinline__ void ins4(float* bv, int* bi, float v, int i) {
#pragma unroll
    for (int s = 0; s < 4; ++s) {
        if (v < bv[s] || (v == bv[s] && i < bi[s])) {
            // shift down
            for (int q = 3; q > s; --q) { bv[q] = bv[q - 1]; bi[q] = bi[q - 1]; }
            bv[s] = v; bi[s] = i;
            return;
        }
    }
}

__global__ void merge_kernel() {
    int row = blockIdx.x * 256 + threadIdx.x;
    float bv[4] = {3.4e38f, 3.4e38f, 3.4e38f, 3.4e38f};
    int   bi[4] = {0, 0, 0, 0};
#pragma unroll
    for (int s = 0; s < KSLOT; ++s) {
        ins4(bv, bi, g_sv1[row * KSLOT + s], g_si1[row * KSLOT + s]);
        ins4(bv, bi, g_sv2[row * KSLOT + s], g_si2[row * KSLOT + s]);
    }
#pragma unroll
    for (int c = 0; c < 4; ++c) g_cand[row * 4 + c] = bi[c];
}

// ---------------------------------------------------------------------------
// K2c: exact fp64 rerank of 4 candidates per row (1 warp per row)
// ---------------------------------------------------------------------------
__global__ void rerank_kernel() {
    int row = blockIdx.x * 8 + (threadIdx.x >> 5);
    int lane = threadIdx.x & 31;
    const float4* xp = (const float4*)&g_X[(size_t)row * DD + lane * 8];
    float4 xa = xp[0], xb = xp[1];
    double s[4];
#pragma unroll
    for (int c = 0; c < 4; ++c) {
        int cd = g_cand[row * 4 + c];
        const float4* ep = (const float4*)&g_EtF[(size_t)cd * DD + lane * 8];
        float4 ea = ep[0], eb = ep[1];
        double t, acc = 0.0;
        t = (double)xa.x - ea.x; acc += t * t;
        t = (double)xa.y - ea.y; acc += t * t;
        t = (double)xa.z - ea.z; acc += t * t;
        t = (double)xa.w - ea.w; acc += t * t;
        t = (double)xb.x - eb.x; acc += t * t;
        t = (double)xb.y - eb.y; acc += t * t;
        t = (double)xb.z - eb.z; acc += t * t;
        t = (double)xb.w - eb.w; acc += t * t;
        s[c] = acc;
    }
#pragma unroll
    for (int o = 16; o; o >>= 1) {
#pragma unroll
        for (int c = 0; c < 4; ++c)
            s[c] += __shfl_down_sync(0xffffffffu, s[c], o);
    }
    if (lane == 0) {
        double bv = s[0]; int bi = g_cand[row * 4];
#pragma unroll
        for (int c = 1; c < 4; ++c) {
            int cd = g_cand[row * 4 + c];
            if (s[c] < bv || (s[c] == bv && cd < bi)) { bv = s[c]; bi = cd; }
        }
        g_idx[row] = bi;
    }
}

// ---------------------------------------------------------------------------
// K4: gather quantize -> out (NCHW), accumulate e_latent_loss
// ---------------------------------------------------------------------------
__global__ void gather_kernel(const float* __restrict__ inputs,
                              const float* __restrict__ embed,
                              float* __restrict__ out) {
    __shared__ int sidx[HW];
    __shared__ float sred[8];
    int b  = blockIdx.x >> 3;
    int d0 = (blockIdx.x & 7) * 32;
    int t  = threadIdx.x;

    for (int i = t; i < HW; i += 256) sidx[i] = g_idx[b * HW + i];
    __syncthreads();

    float lsum = 0.f;
    for (int d = d0; d < d0 + 32; d++) {
        const float* erow = embed + (size_t)d * KK;
        const float* irow = inputs + (size_t)b * DD * HW + (size_t)d * HW;
        float* orow       = out + OUT_OFF + (size_t)b * DD * HW + (size_t)d * HW;
#pragma unroll
        for (int hw = t; hw < HW; hw += 256) {
            float q = erow[sidx[hw]];
            float x = irow[hw];
            orow[hw] = q;
            float df = q - x;
            lsum = fmaf(df, df, lsum);
        }
    }
#pragma unroll
    for (int o = 16; o; o >>= 1) lsum += __shfl_down_sync(0xffffffffu, lsum, o);
    if ((t & 31) == 0) sred[t >> 5] = lsum;
    __syncthreads();
    if (t == 0) {
        float s = 0.f;
#pragma unroll
        for (int i = 0; i < 8; i++) s += sred[i];
        atomicAdd(&g_scal[0], s);
    }
}

// ---------------------------------------------------------------------------
// K5: scatter dw into new_ema_embed; counts histogram
// ---------------------------------------------------------------------------
__global__ void scatter_kernel(float* __restrict__ out) {
    int n = blockIdx.x;
    int d = threadIdx.x;
    int id = g_idx[n];
    float x = g_X[(size_t)n * DD + d];
    atomicAdd(&out[NEWEMA_OFF + (size_t)d * KK + id], 0.01f * x);
    if (d == 0) atomicAdd(&g_counts[id], 1.0f);
}

// ---------------------------------------------------------------------------
// K6: finalize scalars + new_cluster_size + 1/smoothed
// ---------------------------------------------------------------------------
__global__ void finalize_kernel(const float* __restrict__ cs, float* __restrict__ out) {
    __shared__ float sh[32];
    __shared__ float s_n;
    int t = threadIdx.x;
    float ncs_loc[8];
    float nsum = 0.f, psum = 0.f;
#pragma unroll
    for (int i = 0; i < 8; i++) {
        int k = t + i * 1024;
        float c = g_counts[k];
        float v = cs[k] * 0.99f + 0.01f * c;
        out[NCS_OFF + k] = v;
        ncs_loc[i] = v;
        nsum += v;
        float p = c * (1.0f / 32768.0f);
        psum += p * logf(p + 1e-10f);
    }
#pragma unroll
    for (int o = 16; o; o >>= 1) nsum += __shfl_down_sync(0xffffffffu, nsum, o);
    if ((t & 31) == 0) sh[t >> 5] = nsum;
    __syncthreads();
    if (t < 32) {
        float v = sh[t];
#pragma unroll
        for (int o = 16; o; o >>= 1) v += __shfl_down_sync(0xffffffffu, v, o);
        if (t == 0) s_n = v;
    }
    __syncthreads();
    float n = s_n;
#pragma unroll
    for (int i = 0; i < 8; i++) {
        int k = t + i * 1024;
        float v = ncs_loc[i];
        g_invsm[k] = (n + v * 1e-5f) / (n * (v + 1e-5f));
    }
    __syncthreads();
#pragma unroll
    for (int o = 16; o; o >>= 1) psum += __shfl_down_sync(0xffffffffu, psum, o);
    if ((t & 31) == 0) sh[t >> 5] = psum;
    __syncthreads();
    if (t == 0) {
        float p = 0.f;
#pragma unroll
        for (int i = 0; i < 32; i++) p += sh[i];
        out[LOSS_OFF] = 0.25f * g_scal[0] * (1.0f / 8388608.0f);
        out[PERP_OFF] = expf(-p);
    }
}

// ---------------------------------------------------------------------------
// K7: new_embed = new_ema_embed * (1/smoothed)
// ---------------------------------------------------------------------------
__global__ void newembed_kernel(float* __restrict__ out) {
    int i = blockIdx.x * 256 + threadIdx.x;
    int k = i & (KK - 1);
    out[NEWEMB_OFF + i] = out[NEWEMA_OFF + i] * g_invsm[k];
}

// ---------------------------------------------------------------------------
extern "C" void kernel_launch(void* const* d_in, const int* in_sizes, int n_in,
                              void* d_out, int out_size) {
    const float* inputs = (const float*)d_in[0];
    const float* embed  = (const float*)d_in[1];
    const float* cs     = (const float*)d_in[2];
    const float* ema    = (const float*)d_in[3];
    float* out = (float*)d_out;
    (void)in_sizes; (void)n_in; (void)out_size;

    cudaFuncSetAttribute(argmin_mma_kernel,
                         cudaFuncAttributeMaxDynamicSharedMemorySize, SMEM_TOT);

    transpose_kernel<<<dim3(32, 8, 32), dim3(32, 8)>>>(inputs);
    etrans_kernel<<<dim3(KK / 32, DD / 32), dim3(32, 8)>>>(embed);
    enorm_kernel<<<KK / 256, 256>>>(embed);
    init_kernel<<<(DD * KK) / 256, 256>>>(ema, out);
    argmin_mma_kernel<<<(NN / 128) * KSPLIT, 256, SMEM_TOT>>>();
    merge_kernel<<<NN / 256, 256>>>();
    rerank_kernel<<<NN / 8, 256>>>();
    gather_kernel<<<256, 256>>>(inputs, embed, out);
    scatter_kernel<<<NN, DD>>>(out);
    finalize_kernel<<<1, 1024>>>(cs, out);
    newembed_kernel<<<(DD * KK) / 256, 256>>>(out);
}